// round 14
// baseline (speedup 1.0000x reference)
#include <cuda_runtime.h>
#include <cuda_fp16.h>
#include <cfloat>
#include <cstdint>

#define BB 2048
#define TT 32
#define VV 1024
#define DD 256
#define WINF 0.6f
#define CANDMAX 32

// ---------------- static device scratch -------------------------------------
__device__ float g_c2[TT * VV];                                  // 128 KB
// A hi fragments: [t][mtile16(128)][kstep(16)] blocks of 128 half2
__device__ half2 g_xh[(size_t)TT * 128 * 16 * 128];              // 33.5 MB
// B hi fragments: [t][ntile8][kstep(16)] blocks of 64 half2
__device__ half2 g_ch[(size_t)TT * 128 * 16 * 64];               // 16.8 MB

// ---------------- helpers ----------------------------------------------------
__device__ __forceinline__ void mma_f16(float* c, uint32_t a0, uint32_t a1,
                                        uint32_t a2, uint32_t a3,
                                        uint32_t b0, uint32_t b1) {
    asm volatile(
        "mma.sync.aligned.m16n8k16.row.col.f32.f16.f16.f32 "
        "{%0,%1,%2,%3}, {%4,%5,%6,%7}, {%8,%9}, {%0,%1,%2,%3};"
        : "+f"(c[0]), "+f"(c[1]), "+f"(c[2]), "+f"(c[3])
        : "r"(a0), "r"(a1), "r"(a2), "r"(a3), "r"(b0), "r"(b1));
}
__device__ __forceinline__ uint32_t smem_u32(const void* p) {
    uint32_t a;
    asm("{ .reg .u64 t; cvta.to.shared.u64 t, %1; cvt.u32.u64 %0, t; }" : "=r"(a) : "l"(p));
    return a;
}
__device__ __forceinline__ void cp16(uint32_t dst, const void* src) {
    asm volatile("cp.async.cg.shared.global [%0], [%1], 16;" :: "r"(dst), "l"(src));
}
#define CP_COMMIT() asm volatile("cp.async.commit_group;")
#define CP_WAIT(n)  asm volatile("cp.async.wait_group %0;" :: "n"(n))

// order-preserving float <-> uint encoding (for atomicMin)
__device__ __forceinline__ uint32_t fenc(float f) {
    uint32_t u = __float_as_uint(f);
    return (u & 0x80000000u) ? ~u : (u | 0x80000000u);
}
__device__ __forceinline__ float fdec(uint32_t e) {
    uint32_t u = (e & 0x80000000u) ? (e ^ 0x80000000u) : ~e;
    return __uint_as_float(u);
}

// ---------------- prepass: hi-limb split of X and C + c2 ---------------------
__global__ __launch_bounds__(128) void conv_kernel(const float* __restrict__ x,
                                                   const float* __restrict__ cb) {
    __shared__ float sm[16][258];
    __shared__ float psum[16][8];
    const int t = blockIdx.y, tid = threadIdx.x;
    if (blockIdx.x < 128) {
        const int mt = blockIdx.x;
#pragma unroll
        for (int j = 0; j < 8; j++) {
            int f = tid + j * 128;
            int r = f >> 6, d4 = f & 63;
            float4 v = *reinterpret_cast<const float4*>(
                x + ((size_t)(mt * 16 + r) * TT + t) * DD + d4 * 4);
            sm[r][d4 * 4 + 0] = v.x; sm[r][d4 * 4 + 1] = v.y;
            sm[r][d4 * 4 + 2] = v.z; sm[r][d4 * 4 + 3] = v.w;
        }
        __syncthreads();
        const int lane = tid >> 2, r = tid & 3;
        const int tig = lane & 3, grp = lane >> 2;
        const int row = grp + (r & 1) * 8;
        half2* obase = g_xh + ((size_t)(t * 128 + mt) * 16) * 128;
#pragma unroll
        for (int ks = 0; ks < 16; ks++) {
            int k = ks * 16 + (r >> 1) * 8 + tig * 2;
            obase[ks * 128 + tid] = __halves2half2(
                __float2half_rn(sm[row][k]), __float2half_rn(sm[row][k + 1]));
        }
    } else {
        const int vt = blockIdx.x - 128;
#pragma unroll
        for (int j = 0; j < 8; j++) {
            int f = tid + j * 128;
            int r = f >> 6, d4 = f & 63;
            float4 v = *reinterpret_cast<const float4*>(
                cb + ((size_t)t * VV + vt * 16 + r) * DD + d4 * 4);
            sm[r][d4 * 4 + 0] = v.x; sm[r][d4 * 4 + 1] = v.y;
            sm[r][d4 * 4 + 2] = v.z; sm[r][d4 * 4 + 3] = v.w;
        }
        __syncthreads();
        {
            int r = tid >> 3, seg = tid & 7;
            float s = 0.f;
#pragma unroll
            for (int k = 0; k < 32; k++) {
                float v = sm[r][seg * 32 + k];
                s = fmaf(v, v, s);
            }
            psum[r][seg] = s;
        }
        const int s = tid >> 6, w = tid & 63;
        const int lane = w >> 1, rr = w & 1;
        const int grp = lane >> 2, tig = lane & 3;
        const int row = s * 8 + grp;
#pragma unroll
        for (int ks = 0; ks < 16; ks++) {
            int k = ks * 16 + rr * 8 + tig * 2;
            half2* ob = g_ch + ((size_t)(t * 128 + vt * 2 + s) * 16 + ks) * 64;
            ob[w] = __halves2half2(
                __float2half_rn(sm[row][k]), __float2half_rn(sm[row][k + 1]));
        }
        __syncthreads();
        if (tid < 16) {
            float acc = 0.f;
#pragma unroll
            for (int j = 0; j < 8; j++) acc += psum[tid][j];
            g_c2[t * VV + vt * 16 + tid] = acc;
        }
    }
}

// ---------------- fused: hi*hi GEMM + online screen-argmin + refine + gather -
// Grid (16, 32), 256 threads = 8 warps (2m x 4n). Warp 64x32, block 128x128.
#define STAGE_H2 4096                        // half2 per stage (16 KB)
#define NSTAGE 64
#define OFF_C2   49152
#define OFF_RMIN (OFF_C2 + 4096)
#define OFF_RCNT (OFF_RMIN + 512)
#define OFF_LIST (OFF_RCNT + 512)
#define DYN_SMEM (OFF_LIST + 128 * CANDMAX * 4)

__global__ __launch_bounds__(256, 2)
void vsq_fused_kernel(const float* __restrict__ x, const float* __restrict__ cb,
                      float* __restrict__ out) {
    extern __shared__ char dyn[];
    half2*    sbuf   = reinterpret_cast<half2*>(dyn);
    float*    c2c    = reinterpret_cast<float*>(dyn + OFF_C2);
    uint32_t* rowmin = reinterpret_cast<uint32_t*>(dyn + OFF_RMIN);
    int*      rowcnt = reinterpret_cast<int*>(dyn + OFF_RCNT);
    int*      rlist  = reinterpret_cast<int*>(dyn + OFF_LIST);

    const int tid = threadIdx.x;
    const int btile = blockIdx.x, t = blockIdx.y;
    const int wid = tid >> 5, lane = tid & 31;
    const int grp = lane >> 2, tig = lane & 3;
    const int wm = wid >> 2, wn = wid & 3;

    for (int i = tid; i < VV; i += 256) c2c[i] = g_c2[t * VV + i] - 256.0f;
    if (tid < 128) { rowmin[tid] = 0xFFFFFFFFu; rowcnt[tid] = 0; }
    __syncthreads();

    const half2* Abase = g_xh + ((size_t)(t * 128 + btile * 8) * 16) * 128;
    const half2* Bbase = g_ch + ((size_t)(t * 128)) * 16 * 64;

    const uint32_t sb0 = smem_u32(sbuf);
    const int nt8 = wid * 2 + (lane >> 4);
    const int bsub = (lane & 15) * 4;
    auto stage = [&](int st, int buf) {
        const int nch = st >> 3, ks0 = (st & 7) * 2;
        uint32_t d = sb0 + (uint32_t)buf * STAGE_H2 * 4;
#pragma unroll
        for (int sub = 0; sub < 2; sub++) {
            int ks = ks0 + sub;
            cp16(d + (sub * 1024 + wid * 128 + lane * 4) * 4,
                 Abase + ((size_t)(wid * 16 + ks)) * 128 + lane * 4);
            cp16(d + (2048 + sub * 1024 + nt8 * 64 + bsub) * 4,
                 Bbase + ((size_t)((nch * 16 + nt8) * 16 + ks)) * 64 + bsub);
        }
        CP_COMMIT();
    };

    stage(0, 0);
    stage(1, 1);

    float acc[4][4][4];
#pragma unroll
    for (int a = 0; a < 4; a++)
#pragma unroll
        for (int b = 0; b < 4; b++)
#pragma unroll
            for (int c = 0; c < 4; c++) acc[a][b][c] = 0.f;

    for (int s = 0; s < NSTAGE; s++) {
        if (s < NSTAGE - 2) { CP_WAIT(1); } else { CP_WAIT(0); }
        __syncthreads();
        if (s + 2 < NSTAGE) stage(s + 2, (s + 2) % 3);

        const int buf = s % 3;
#pragma unroll
        for (int sub = 0; sub < 2; sub++) {
            half2* Asm = sbuf + buf * STAGE_H2 + sub * 1024;
            half2* Bsm = sbuf + buf * STAGE_H2 + 2048 + sub * 1024;
            uint4 AH[4];
            uint2 BH[4];
#pragma unroll
            for (int mt = 0; mt < 4; mt++)
                AH[mt] = *reinterpret_cast<uint4*>(Asm + (wm * 4 + mt) * 128 + lane * 4);
#pragma unroll
            for (int q = 0; q < 4; q++)
                BH[q] = *reinterpret_cast<uint2*>(Bsm + (wn * 4 + q) * 64 + lane * 2);
#pragma unroll
            for (int q = 0; q < 4; q++)
#pragma unroll
                for (int mt = 0; mt < 4; mt++)
                    mma_f16(acc[mt][q], AH[mt].x, AH[mt].y, AH[mt].z, AH[mt].w,
                            BH[q].x, BH[q].y);
        }

        if ((s & 7) == 7) {
            const int nch = s >> 3;
            float sc[4][4][4];
            // pass 1: scores + rowmin atomicMin
#pragma unroll
            for (int q = 0; q < 4; q++) {
                int v = nch * 128 + wn * 32 + q * 8 + tig * 2;
                float c0 = c2c[v], c1 = c2c[v + 1];
#pragma unroll
                for (int mt = 0; mt < 4; mt++) {
                    int r0 = wm * 64 + mt * 16 + grp;
                    sc[mt][q][0] = fmaf(-2.f, acc[mt][q][0], c0);
                    sc[mt][q][1] = fmaf(-2.f, acc[mt][q][1], c1);
                    sc[mt][q][2] = fmaf(-2.f, acc[mt][q][2], c0);
                    sc[mt][q][3] = fmaf(-2.f, acc[mt][q][3], c1);
                    float m01 = fminf(sc[mt][q][0], sc[mt][q][1]);
                    float m23 = fminf(sc[mt][q][2], sc[mt][q][3]);
                    atomicMin(&rowmin[r0], fenc(m01));
                    atomicMin(&rowmin[r0 + 8], fenc(m23));
                    acc[mt][q][0] = 0.f; acc[mt][q][1] = 0.f;
                    acc[mt][q][2] = 0.f; acc[mt][q][3] = 0.f;
                }
            }
            __syncthreads();
            // pass 2: collect candidates within window of current rowmin
#pragma unroll
            for (int mt = 0; mt < 4; mt++) {
                int r0 = wm * 64 + mt * 16 + grp;
                float w0 = fdec(rowmin[r0]) + WINF;
                float w1 = fdec(rowmin[r0 + 8]) + WINF;
#pragma unroll
                for (int q = 0; q < 4; q++) {
                    int v = nch * 128 + wn * 32 + q * 8 + tig * 2;
                    if (sc[mt][q][0] <= w0) {
                        int p = atomicAdd(&rowcnt[r0], 1);
                        if (p < CANDMAX) rlist[r0 * CANDMAX + p] = v;
                    }
                    if (sc[mt][q][1] <= w0) {
                        int p = atomicAdd(&rowcnt[r0], 1);
                        if (p < CANDMAX) rlist[r0 * CANDMAX + p] = v + 1;
                    }
                    if (sc[mt][q][2] <= w1) {
                        int p = atomicAdd(&rowcnt[r0 + 8], 1);
                        if (p < CANDMAX) rlist[(r0 + 8) * CANDMAX + p] = v;
                    }
                    if (sc[mt][q][3] <= w1) {
                        int p = atomicAdd(&rowcnt[r0 + 8], 1);
                        if (p < CANDMAX) rlist[(r0 + 8) * CANDMAX + p] = v + 1;
                    }
                }
            }
        }
    }

    // final epilogue: per-row resolve + gather. Warp wid owns rows wid*16..+15.
    __syncthreads();
    for (int i = 0; i < 16; i++) {
        const int r = wid * 16 + i;
        const int b = btile * 128 + r;
        int cnt = rowcnt[r];
        int idx;
        if (cnt == 1) {
            idx = rlist[r * CANDMAX];
        } else {
            // exact fp32 refine
            const float* xr = x + ((size_t)b * TT + t) * DD;
            float4 x0 = reinterpret_cast<const float4*>(xr)[lane * 2];
            float4 x1 = reinterpret_cast<const float4*>(xr)[lane * 2 + 1];
            float bestf = FLT_MAX;
            int   bwi = 0x7fffffff;
            if (cnt <= CANDMAX) {
                for (int c = 0; c < cnt; c++) {
                    int v = rlist[r * CANDMAX + c];
                    const float* cr = cb + ((size_t)t * VV + v) * DD;
                    float4 c0 = reinterpret_cast<const float4*>(cr)[lane * 2];
                    float4 c1 = reinterpret_cast<const float4*>(cr)[lane * 2 + 1];
                    float p = 0.f;
                    p = fmaf(x0.x, c0.x, p); p = fmaf(x0.y, c0.y, p);
                    p = fmaf(x0.z, c0.z, p); p = fmaf(x0.w, c0.w, p);
                    p = fmaf(x1.x, c1.x, p); p = fmaf(x1.y, c1.y, p);
                    p = fmaf(x1.z, c1.z, p); p = fmaf(x1.w, c1.w, p);
#pragma unroll
                    for (int off = 16; off > 0; off >>= 1)
                        p += __shfl_xor_sync(0xffffffffu, p, off);
                    float scx = fmaf(-2.f, p, g_c2[t * VV + v]);
                    if (scx < bestf || (scx == bestf && v < bwi)) { bestf = scx; bwi = v; }
                }
            } else {
                // overflow fallback: exact scan of all 1024 (essentially never)
                for (int v = 0; v < VV; v++) {
                    const float* cr = cb + ((size_t)t * VV + v) * DD;
                    float4 c0 = reinterpret_cast<const float4*>(cr)[lane * 2];
                    float4 c1 = reinterpret_cast<const float4*>(cr)[lane * 2 + 1];
                    float p = 0.f;
                    p = fmaf(x0.x, c0.x, p); p = fmaf(x0.y, c0.y, p);
                    p = fmaf(x0.z, c0.z, p); p = fmaf(x0.w, c0.w, p);
                    p = fmaf(x1.x, c1.x, p); p = fmaf(x1.y, c1.y, p);
                    p = fmaf(x1.z, c1.z, p); p = fmaf(x1.w, c1.w, p);
#pragma unroll
                    for (int off = 16; off > 0; off >>= 1)
                        p += __shfl_xor_sync(0xffffffffu, p, off);
                    float scx = fmaf(-2.f, p, g_c2[t * VV + v]);
                    if (scx < bestf) { bestf = scx; bwi = v; }
                }
            }
            idx = bwi;
        }

        if (lane == 0)
            out[(size_t)BB * TT * DD + (size_t)b * TT + t] = (float)idx;
        const float4* src = reinterpret_cast<const float4*>(
            cb + ((size_t)t * VV + idx) * DD);
        float4* dst = reinterpret_cast<float4*>(out + ((size_t)b * TT + t) * DD);
        dst[lane]      = src[lane];
        dst[lane + 32] = src[lane + 32];
    }
}

// ---------------------------------------------------------------------------
extern "C" void kernel_launch(void* const* d_in, const int* in_sizes, int n_in,
                              void* d_out, int out_size) {
    const float* x  = (const float*)d_in[0];   // (B, T, D) f32
    const float* cb = (const float*)d_in[1];   // (T, V, D) f32
    float* out = (float*)d_out;

    cudaFuncSetAttribute(vsq_fused_kernel, cudaFuncAttributeMaxDynamicSharedMemorySize, DYN_SMEM);
    conv_kernel<<<dim3(192, TT), 128>>>(x, cb);
    vsq_fused_kernel<<<dim3(BB / 128, TT), 256, DYN_SMEM>>>(x, cb, out);
}

// round 15
// speedup vs baseline: 1.1826x; 1.1826x over previous
#include <cuda_runtime.h>
#include <cuda_fp16.h>
#include <cfloat>
#include <cstdint>

#define BB 2048
#define TT 32
#define VV 1024
#define DD 256
#define WINF 0.6f

// ---------------- static device scratch -------------------------------------
__device__ float g_c2[TT * VV];                                  // 128 KB
__device__ float g_rmin[TT * BB];                                // 256 KB
// A hi fragments: [t][mtile16(128)][kstep(16)] blocks of 128 half2
__device__ half2 g_xh[(size_t)TT * 128 * 16 * 128];              // 33.5 MB
// B hi fragments: [t][ntile8][kstep(16)] blocks of 64 half2
__device__ half2 g_ch[(size_t)TT * 128 * 16 * 64];               // 16.8 MB
// screened centered scores, fp16: [t][b][v]
__device__ __half g_sc[(size_t)TT * BB * VV];                    // 128 MB

// ---------------- helpers ----------------------------------------------------
__device__ __forceinline__ void mma_f16(float* c, uint32_t a0, uint32_t a1,
                                        uint32_t a2, uint32_t a3,
                                        uint32_t b0, uint32_t b1) {
    asm volatile(
        "mma.sync.aligned.m16n8k16.row.col.f32.f16.f16.f32 "
        "{%0,%1,%2,%3}, {%4,%5,%6,%7}, {%8,%9}, {%0,%1,%2,%3};"
        : "+f"(c[0]), "+f"(c[1]), "+f"(c[2]), "+f"(c[3])
        : "r"(a0), "r"(a1), "r"(a2), "r"(a3), "r"(b0), "r"(b1));
}
__device__ __forceinline__ uint32_t smem_u32(const void* p) {
    uint32_t a;
    asm("{ .reg .u64 t; cvta.to.shared.u64 t, %1; cvt.u32.u64 %0, t; }" : "=r"(a) : "l"(p));
    return a;
}
__device__ __forceinline__ void cp16(uint32_t dst, const void* src) {
    asm volatile("cp.async.cg.shared.global [%0], [%1], 16;" :: "r"(dst), "l"(src));
}
#define CP_COMMIT() asm volatile("cp.async.commit_group;")
#define CP_WAIT(n)  asm volatile("cp.async.wait_group %0;" :: "n"(n))

// ---------------- prepass: hi-limb split of X and C + c2 ---------------------
__global__ __launch_bounds__(128) void conv_kernel(const float* __restrict__ x,
                                                   const float* __restrict__ cb) {
    __shared__ float sm[16][258];
    __shared__ float psum[16][8];
    const int t = blockIdx.y, tid = threadIdx.x;
    if (blockIdx.x < 128) {
        const int mt = blockIdx.x;
#pragma unroll
        for (int j = 0; j < 8; j++) {
            int f = tid + j * 128;
            int r = f >> 6, d4 = f & 63;
            float4 v = *reinterpret_cast<const float4*>(
                x + ((size_t)(mt * 16 + r) * TT + t) * DD + d4 * 4);
            sm[r][d4 * 4 + 0] = v.x; sm[r][d4 * 4 + 1] = v.y;
            sm[r][d4 * 4 + 2] = v.z; sm[r][d4 * 4 + 3] = v.w;
        }
        __syncthreads();
        const int lane = tid >> 2, r = tid & 3;
        const int tig = lane & 3, grp = lane >> 2;
        const int row = grp + (r & 1) * 8;
        half2* obase = g_xh + ((size_t)(t * 128 + mt) * 16) * 128;
#pragma unroll
        for (int ks = 0; ks < 16; ks++) {
            int k = ks * 16 + (r >> 1) * 8 + tig * 2;
            obase[ks * 128 + tid] = __halves2half2(
                __float2half_rn(sm[row][k]), __float2half_rn(sm[row][k + 1]));
        }
    } else {
        const int vt = blockIdx.x - 128;
#pragma unroll
        for (int j = 0; j < 8; j++) {
            int f = tid + j * 128;
            int r = f >> 6, d4 = f & 63;
            float4 v = *reinterpret_cast<const float4*>(
                cb + ((size_t)t * VV + vt * 16 + r) * DD + d4 * 4);
            sm[r][d4 * 4 + 0] = v.x; sm[r][d4 * 4 + 1] = v.y;
            sm[r][d4 * 4 + 2] = v.z; sm[r][d4 * 4 + 3] = v.w;
        }
        __syncthreads();
        {
            int r = tid >> 3, seg = tid & 7;
            float s = 0.f;
#pragma unroll
            for (int k = 0; k < 32; k++) {
                float v = sm[r][seg * 32 + k];
                s = fmaf(v, v, s);
            }
            psum[r][seg] = s;
        }
        const int s = tid >> 6, w = tid & 63;
        const int lane = w >> 1, rr = w & 1;
        const int grp = lane >> 2, tig = lane & 3;
        const int row = s * 8 + grp;
#pragma unroll
        for (int ks = 0; ks < 16; ks++) {
            int k = ks * 16 + rr * 8 + tig * 2;
            half2* ob = g_ch + ((size_t)(t * 128 + vt * 2 + s) * 16 + ks) * 64;
            ob[w] = __halves2half2(
                __float2half_rn(sm[row][k]), __float2half_rn(sm[row][k + 1]));
        }
        __syncthreads();
        if (tid < 16) {
            float acc = 0.f;
#pragma unroll
            for (int j = 0; j < 8; j++) acc += psum[tid][j];
            g_c2[t * VV + vt * 16 + tid] = acc;
        }
    }
}

// ---------------- phase 1: hi*hi GEMM -> fp16 scores + register row-min ------
#define STAGE_H2 4096                        // half2 per stage (16 KB)
#define NSTAGE 64
#define DYN_SMEM (49152 + 4096 + 8192)       // bufs + c2c + Sv alias headroom

__global__ __launch_bounds__(256, 2)
void vsq_score_kernel(float* __restrict__ dummy) {
    extern __shared__ char dyn[];
    half2* sbuf = reinterpret_cast<half2*>(dyn);            // 3 x 16KB
    float* c2c  = reinterpret_cast<float*>(dyn + 49152);    // 4KB (c2 - 256)
    float* Sv   = reinterpret_cast<float*>(dyn);            // [128][16] (alias)

    const int tid = threadIdx.x;
    const int btile = blockIdx.x, t = blockIdx.y;
    const int wid = tid >> 5, lane = tid & 31;
    const int grp = lane >> 2, tig = lane & 3;
    const int wm = wid >> 2, wn = wid & 3;

    for (int i = tid; i < VV; i += 256) c2c[i] = g_c2[t * VV + i] - 256.0f;
    __syncthreads();

    const half2* Abase = g_xh + ((size_t)(t * 128 + btile * 8) * 16) * 128;
    const half2* Bbase = g_ch + ((size_t)(t * 128)) * 16 * 64;

    const uint32_t sb0 = smem_u32(sbuf);
    const int nt8 = wid * 2 + (lane >> 4);
    const int bsub = (lane & 15) * 4;
    auto stage = [&](int st, int buf) {
        const int nch = st >> 3, ks0 = (st & 7) * 2;
        uint32_t d = sb0 + (uint32_t)buf * STAGE_H2 * 4;
#pragma unroll
        for (int sub = 0; sub < 2; sub++) {
            int ks = ks0 + sub;
            cp16(d + (sub * 1024 + wid * 128 + lane * 4) * 4,
                 Abase + ((size_t)(wid * 16 + ks)) * 128 + lane * 4);
            cp16(d + (2048 + sub * 1024 + nt8 * 64 + bsub) * 4,
                 Bbase + ((size_t)((nch * 16 + nt8) * 16 + ks)) * 64 + bsub);
        }
        CP_COMMIT();
    };

    stage(0, 0);
    stage(1, 1);

    float acc[4][4][4];
#pragma unroll
    for (int a = 0; a < 4; a++)
#pragma unroll
        for (int b = 0; b < 4; b++)
#pragma unroll
            for (int c = 0; c < 4; c++) acc[a][b][c] = 0.f;

    float bmin[8];
#pragma unroll
    for (int i = 0; i < 8; i++) bmin[i] = FLT_MAX;

    const size_t srowbase = (size_t)t * BB + (size_t)btile * 128;

    for (int s = 0; s < NSTAGE; s++) {
        if (s < NSTAGE - 2) { CP_WAIT(1); } else { CP_WAIT(0); }
        __syncthreads();
        if (s + 2 < NSTAGE) stage(s + 2, (s + 2) % 3);

        const int buf = s % 3;
#pragma unroll
        for (int sub = 0; sub < 2; sub++) {
            half2* Asm = sbuf + buf * STAGE_H2 + sub * 1024;
            half2* Bsm = sbuf + buf * STAGE_H2 + 2048 + sub * 1024;
            uint4 AH[4];
            uint2 BH[4];
#pragma unroll
            for (int mt = 0; mt < 4; mt++)
                AH[mt] = *reinterpret_cast<uint4*>(Asm + (wm * 4 + mt) * 128 + lane * 4);
#pragma unroll
            for (int q = 0; q < 4; q++)
                BH[q] = *reinterpret_cast<uint2*>(Bsm + (wn * 4 + q) * 64 + lane * 2);
#pragma unroll
            for (int q = 0; q < 4; q++)
#pragma unroll
                for (int mt = 0; mt < 4; mt++)
                    mma_f16(acc[mt][q], AH[mt].x, AH[mt].y, AH[mt].z, AH[mt].w,
                            BH[q].x, BH[q].y);
        }

        if ((s & 7) == 7) {
            const int nch = s >> 3;
#pragma unroll
            for (int q = 0; q < 4; q++) {
                int v = nch * 128 + wn * 32 + q * 8 + tig * 2;
                float c0 = c2c[v], c1 = c2c[v + 1];
#pragma unroll
                for (int mt = 0; mt < 4; mt++) {
                    int r0 = wm * 64 + mt * 16 + grp;
                    float s0 = fmaf(-2.f, acc[mt][q][0], c0);
                    float s1 = fmaf(-2.f, acc[mt][q][1], c1);
                    float s2 = fmaf(-2.f, acc[mt][q][2], c0);
                    float s3 = fmaf(-2.f, acc[mt][q][3], c1);
                    bmin[mt * 2]     = fminf(bmin[mt * 2], fminf(s0, s1));
                    bmin[mt * 2 + 1] = fminf(bmin[mt * 2 + 1], fminf(s2, s3));
                    *reinterpret_cast<__half2*>(&g_sc[(srowbase + r0) * VV + v]) =
                        __floats2half2_rn(s0, s1);
                    *reinterpret_cast<__half2*>(&g_sc[(srowbase + r0 + 8) * VV + v]) =
                        __floats2half2_rn(s2, s3);
                    acc[mt][q][0] = 0.f; acc[mt][q][1] = 0.f;
                    acc[mt][q][2] = 0.f; acc[mt][q][3] = 0.f;
                }
            }
        }
    }

    // row-min reduce (16 contributors per row) -> g_rmin
    __syncthreads();
#pragma unroll
    for (int mt = 0; mt < 4; mt++) {
#pragma unroll
        for (int h = 0; h < 2; h++) {
            int r = wm * 64 + mt * 16 + grp + h * 8;
            Sv[r * 16 + wn * 4 + tig] = bmin[mt * 2 + h];
        }
    }
    __syncthreads();
    if (tid < 128) {
        float bv = Sv[tid * 16];
#pragma unroll
        for (int u = 1; u < 16; u++) bv = fminf(bv, Sv[tid * 16 + u]);
        g_rmin[srowbase + tid] = bv;
    }
}

// ---------------- phase 2: window scan + exact refine + gather ---------------
// Grid (64, 32), 256 threads = 8 warps; warp handles 4 rows sequentially.
__global__ __launch_bounds__(256)
void argmin_kernel(const float* __restrict__ x, const float* __restrict__ cb,
                   float* __restrict__ out) {
    __shared__ int s_list[8][40];
    __shared__ int s_cnt[8];
    const int tid = threadIdx.x, w = tid >> 5, lane = tid & 31;
    const int t = blockIdx.y;

    for (int r = 0; r < 4; r++) {
        const int b = blockIdx.x * 32 + w * 4 + r;
        const __half* srow = g_sc + ((size_t)t * BB + b) * VV;
        const uint4* srow4 = reinterpret_cast<const uint4*>(srow);
        const float win = g_rmin[(size_t)t * BB + b] + WINF;

        if (lane == 0) s_cnt[w] = 0;
        __syncwarp();

#pragma unroll
        for (int i = 0; i < 4; i++) {
            uint4 qv = srow4[i * 32 + lane];
            const uint32_t* u = reinterpret_cast<const uint32_t*>(&qv);
#pragma unroll
            for (int wd = 0; wd < 4; wd++) {
                __half2 h2 = *reinterpret_cast<const __half2*>(&u[wd]);
                float f0 = __low2float(h2), f1 = __high2float(h2);
                int v0 = i * 256 + lane * 8 + wd * 2;
                if (f0 <= win) {
                    int pos = atomicAdd(&s_cnt[w], 1);
                    if (pos < 40) s_list[w][pos] = v0;
                }
                if (f1 <= win) {
                    int pos = atomicAdd(&s_cnt[w], 1);
                    if (pos < 40) s_list[w][pos] = v0 + 1;
                }
            }
        }
        __syncwarp();
        int cnt = s_cnt[w];

        int widx;
        if (cnt == 1) {
            widx = s_list[w][0];
        } else {
            const float* xr = x + ((size_t)b * TT + t) * DD;
            float4 x0 = reinterpret_cast<const float4*>(xr)[lane * 2];
            float4 x1 = reinterpret_cast<const float4*>(xr)[lane * 2 + 1];
            float bestf = FLT_MAX;
            int   bwi = 0x7fffffff;
            if (cnt <= 40) {
                for (int c = 0; c < cnt; c++) {
                    int v = s_list[w][c];
                    const float* cr = cb + ((size_t)t * VV + v) * DD;
                    float4 c0 = reinterpret_cast<const float4*>(cr)[lane * 2];
                    float4 c1 = reinterpret_cast<const float4*>(cr)[lane * 2 + 1];
                    float p = 0.f;
                    p = fmaf(x0.x, c0.x, p); p = fmaf(x0.y, c0.y, p);
                    p = fmaf(x0.z, c0.z, p); p = fmaf(x0.w, c0.w, p);
                    p = fmaf(x1.x, c1.x, p); p = fmaf(x1.y, c1.y, p);
                    p = fmaf(x1.z, c1.z, p); p = fmaf(x1.w, c1.w, p);
#pragma unroll
                    for (int off = 16; off > 0; off >>= 1)
                        p += __shfl_xor_sync(0xffffffffu, p, off);
                    float sc = fmaf(-2.f, p, g_c2[t * VV + v]);
                    if (sc < bestf || (sc == bestf && v < bwi)) { bestf = sc; bwi = v; }
                }
            } else {
                // overflow fallback: exact scan of all 1024 (essentially never)
                for (int v = 0; v < VV; v++) {
                    const float* cr = cb + ((size_t)t * VV + v) * DD;
                    float4 c0 = reinterpret_cast<const float4*>(cr)[lane * 2];
                    float4 c1 = reinterpret_cast<const float4*>(cr)[lane * 2 + 1];
                    float p = 0.f;
                    p = fmaf(x0.x, c0.x, p); p = fmaf(x0.y, c0.y, p);
                    p = fmaf(x0.z, c0.z, p); p = fmaf(x0.w, c0.w, p);
                    p = fmaf(x1.x, c1.x, p); p = fmaf(x1.y, c1.y, p);
                    p = fmaf(x1.z, c1.z, p); p = fmaf(x1.w, c1.w, p);
#pragma unroll
                    for (int off = 16; off > 0; off >>= 1)
                        p += __shfl_xor_sync(0xffffffffu, p, off);
                    float sc = fmaf(-2.f, p, g_c2[t * VV + v]);
                    if (sc < bestf) { bestf = sc; bwi = v; }
                }
            }
            widx = bwi;
        }

        if (lane == 0)
            out[(size_t)BB * TT * DD + (size_t)b * TT + t] = (float)widx;
        const float4* src = reinterpret_cast<const float4*>(
            cb + ((size_t)t * VV + widx) * DD);
        float4* dst = reinterpret_cast<float4*>(out + ((size_t)b * TT + t) * DD);
        dst[lane]      = src[lane];
        dst[lane + 32] = src[lane + 32];
    }
}

// ---------------------------------------------------------------------------
extern "C" void kernel_launch(void* const* d_in, const int* in_sizes, int n_in,
                              void* d_out, int out_size) {
    const float* x  = (const float*)d_in[0];   // (B, T, D) f32
    const float* cb = (const float*)d_in[1];   // (T, V, D) f32
    float* out = (float*)d_out;

    cudaFuncSetAttribute(vsq_score_kernel, cudaFuncAttributeMaxDynamicSharedMemorySize, DYN_SMEM);
    conv_kernel<<<dim3(192, TT), 128>>>(x, cb);
    vsq_score_kernel<<<dim3(BB / 128, TT), 256, DYN_SMEM>>>(out);
    argmin_kernel<<<dim3(64, TT), 256>>>(x, cb, out);
}